// round 13
// baseline (speedup 1.0000x reference)
#include <cuda_runtime.h>
#include <cuda_bf16.h>
#include <cstdint>
#include <math.h>

#define TL 2048
#define EMB 256
#define HD 256           // per-direction hidden
#define NT 7
#define TAG_START 5
#define TAG_END 6
#define NEGV -10000.0f
#define NCHUNK 16
#define CS 128           // chunk size (TL / NCHUNK)
#define CLN 16           // cluster size for lstm

// Scratch (device globals; no allocation allowed)
__device__ float g_gin[2 * TL * 1024];    // [dir][t][perm] permuted input projections
__device__ float g_hs[2 * TL * HD];       // [dir][t][HD]
__device__ float g_feats[TL * NT];
__device__ float g_M[NCHUNK][NT][NT];     // max-plus chunk matrices
__device__ float g_fvb[NCHUNK][NT];       // fv entering each chunk
__device__ float g_final[2];              // [path_score, final_tag]
__device__ unsigned char g_cand[NCHUNK][NT][CS];  // candidate paths per end-tag
__device__ unsigned char g_exit[NCHUNK][NT];      // exit tag per end-tag hypothesis

// ---------------------------------------------------------------------------
// PTX helpers
// ---------------------------------------------------------------------------
__device__ __forceinline__ uint32_t smem_u32(const void* p) {
    uint32_t a;
    asm("{ .reg .u64 t; cvta.to.shared.u64 t, %1; cvt.u32.u64 %0, t; }" : "=r"(a) : "l"(p));
    return a;
}
__device__ __forceinline__ uint32_t mapa_u32(uint32_t addr, uint32_t rank) {
    uint32_t r;
    asm("mapa.shared::cluster.u32 %0, %1, %2;" : "=r"(r) : "r"(addr), "r"(rank));
    return r;
}
__device__ __forceinline__ uint32_t my_ctarank() {
    uint32_t r;
    asm("mov.u32 %0, %%cluster_ctarank;" : "=r"(r));
    return r;
}
__device__ __forceinline__ void cluster_sync_all() {
    asm volatile("barrier.cluster.arrive.aligned;" ::: "memory");
    asm volatile("barrier.cluster.wait.aligned;" ::: "memory");
}
__device__ __forceinline__ void mbar_init(uint32_t a, uint32_t n) {
    asm volatile("mbarrier.init.shared.b64 [%0], %1;" :: "r"(a), "r"(n) : "memory");
}
__device__ __forceinline__ void mbar_expect(uint32_t a, uint32_t tx) {
    asm volatile("mbarrier.arrive.expect_tx.shared.b64 _, [%0], %1;" :: "r"(a), "r"(tx) : "memory");
}
__device__ __forceinline__ void mbar_wait(uint32_t a, uint32_t phase) {
    uint32_t done;
    asm volatile(
        "{\n\t.reg .pred p;\n\t"
        "mbarrier.try_wait.parity.acquire.cta.shared::cta.b64 p, [%1], %2;\n\t"
        "selp.b32 %0, 1, 0, p;\n\t}"
        : "=r"(done) : "r"(a), "r"(phase) : "memory");
    if (!done) {
        asm volatile(
            "{\n\t.reg .pred P;\n"
            "W%=:\n\t"
            "mbarrier.try_wait.parity.acquire.cta.shared::cta.b64 P, [%0], %1, 0x989680;\n\t"
            "@P bra D%=;\n\t"
            "bra W%=;\n"
            "D%=:\n\t}"
            :: "r"(a), "r"(phase) : "memory");
    }
}
__device__ __forceinline__ void st_async_u64(uint32_t daddr, unsigned long long v, uint32_t baddr) {
    asm volatile("st.async.shared::cluster.mbarrier::complete_tx::bytes.u64 [%0], %1, [%2];"
                 :: "r"(daddr), "l"(v), "r"(baddr) : "memory");
}
__device__ __forceinline__ void fma2(unsigned long long& d, unsigned long long a, unsigned long long b) {
    asm("fma.rn.f32x2 %0, %1, %2, %0;" : "+l"(d) : "l"(a), "l"(b));
}
__device__ __forceinline__ unsigned long long add2(unsigned long long a, unsigned long long b) {
    unsigned long long r;
    asm("add.rn.f32x2 %0, %1, %2;" : "=l"(r) : "l"(a), "l"(b));
    return r;
}
__device__ __forceinline__ float sum2(unsigned long long v) {
    uint32_t lo, hi;
    asm("mov.b64 {%0, %1}, %2;" : "=r"(lo), "=r"(hi) : "l"(v));
    return __uint_as_float(lo) + __uint_as_float(hi);
}
// fast activations: EX2-based exp + approx reciprocal (~2^-21 rel err)
__device__ __forceinline__ float sig_f(float x) {
    return __fdividef(1.f, 1.f + __expf(-x));
}
__device__ __forceinline__ float tanh_f(float x) {
    return 1.f - __fdividef(2.f, __expf(2.f * x) + 1.f);
}

// ---------------------------------------------------------------------------
// K1: input projection GEMM -> permuted layout matching K2's read order:
// perm index p = (row & 255) * 4 + (row >> 8)   (unit_global*4 + gate)
// ---------------------------------------------------------------------------
__global__ __launch_bounds__(256) void gin_gemm(
    const int* __restrict__ words, const float* __restrict__ embed,
    const float* __restrict__ Wf, const float* __restrict__ bif, const float* __restrict__ bhf,
    const float* __restrict__ Wb, const float* __restrict__ bib, const float* __restrict__ bhb)
{
    const int dir = blockIdx.z;
    const float* W  = dir ? Wb  : Wf;
    const float* bi = dir ? bib : bif;
    const float* bh = dir ? bhb : bhf;
    const int t0  = blockIdx.x * 128;
    const int r0  = blockIdx.y * 128;

    __shared__ float Xs[128][33];
    __shared__ float Ws[128][33];
    __shared__ int   sw[128];

    const int tid = threadIdx.x;
    const int tx = tid & 15, ty = tid >> 4;

    if (tid < 128) sw[tid] = words[t0 + tid];

    float acc[8][8];
#pragma unroll
    for (int i = 0; i < 8; i++)
#pragma unroll
        for (int j = 0; j < 8; j++) acc[i][j] = 0.f;

    for (int kb = 0; kb < EMB; kb += 32) {
        __syncthreads();
#pragma unroll
        for (int it = 0; it < 16; it++) {
            int idx = tid + it * 256;
            int r = idx >> 5, k = idx & 31;
            Xs[r][k] = embed[(size_t)sw[r] * EMB + kb + k];
        }
#pragma unroll
        for (int it = 0; it < 16; it++) {
            int idx = tid + it * 256;
            int r = idx >> 5, k = idx & 31;
            Ws[r][k] = W[(size_t)(r0 + r) * EMB + kb + k];
        }
        __syncthreads();
#pragma unroll
        for (int k = 0; k < 32; k++) {
            float xr[8], wr[8];
#pragma unroll
            for (int i = 0; i < 8; i++) xr[i] = Xs[ty + i * 16][k];
#pragma unroll
            for (int j = 0; j < 8; j++) wr[j] = Ws[tx + j * 16][k];
#pragma unroll
            for (int i = 0; i < 8; i++)
#pragma unroll
                for (int j = 0; j < 8; j++) acc[i][j] = fmaf(xr[i], wr[j], acc[i][j]);
        }
    }
#pragma unroll
    for (int j = 0; j < 8; j++) {
        int row = r0 + tx + j * 16;
        float bb = bi[row] + bh[row];
        int p = (row & 255) * 4 + (row >> 8);
#pragma unroll
        for (int i = 0; i < 8; i++) {
            int t = t0 + ty + i * 16;
            g_gin[((size_t)dir * TL + t) * 1024 + p] = acc[i][j] + bb;
        }
    }
}

// ---------------------------------------------------------------------------
// K2: sequential BiLSTM. Two 16-CTA clusters (one per direction), 128 thr/CTA.
// Each CTA: 16 units = 64 gate rows. u = tid>>3, sub = tid&7, gate = sub>>1,
// half = sub&1. Whh half-row (128 floats) in registers as 64 f32x2.
// h broadcast: unit-pairs packed u64 via st.async; even-u groups -> ranks 0-7,
// odd-u groups -> ranks 8-15.
// SPLIT BARRIERS: 4 mbarriers bar(parity, srchalf). Senders with crank<8 feed
// h[0:128] and signal barrier half A; crank>=8 feed h[128:256] -> half B.
// Thread half=0 reads only h[0:128] -> waits A; half=1 waits B. expect_tx=512B.
// The other half's arrivals overlap this half's dot; rendezvous at shfl.
// gin prefetched 2 steps ahead. Branchless activation; 8-acc FFMA2 dot;
// packed f32x2 reduction tree.
// ---------------------------------------------------------------------------
__global__ __launch_bounds__(128, 1) __cluster_dims__(CLN, 1, 1)
void lstm_kernel(const float* __restrict__ Whf, const float* __restrict__ Whb,
                 const float* __restrict__ h0, const float* __restrict__ c0)
{
    __shared__ __align__(16) float hbuf[2 * HD];
    __shared__ __align__(8) unsigned long long bars[4];   // [parity][half]

    const int tid = threadIdx.x;
    const int dir = blockIdx.x >> 4;
    const uint32_t crank = my_ctarank();

    const int u    = tid >> 3;        // 0..15 local unit
    const int sub  = tid & 7;         // lane within unit group
    const int gate = sub >> 1;        // 0..3
    const int half = sub & 1;         // k-half this thread READS
    const int lane = tid & 31;
    const int uglob = 16 * (int)crank + u;
    const int grow = gate * 256 + uglob;           // global gate row
    const float* Wh = dir ? Whb : Whf;

    // branchless activation constants: a = k1 * sig(k2*v) + k0
    const float k2 = (gate == 2) ? 2.f : 1.f;
    const float k1 = k2;
    const float k0 = (gate == 2) ? -1.f : 0.f;

    // Whh half-row -> registers: 128 floats as 64 f32x2
    unsigned long long w[64];
    {
        const unsigned long long* wp =
            (const unsigned long long*)(Wh + (size_t)grow * HD + (half << 7));
#pragma unroll
        for (int j = 0; j < 64; j++) w[j] = wp[j];
    }

    // init: h(-1) in slot 1 (prev at s=0); c0 redundant on all 8 lanes of group
    hbuf[HD + tid] = h0[dir * HD + tid];
    hbuf[HD + 128 + tid] = h0[dir * HD + 128 + tid];
    float creg = c0[dir * HD + uglob];

    const uint32_t hloc = smem_u32(hbuf);
    const uint32_t bar0 = smem_u32(&bars[0]);
    const uint32_t rank = (u & 1) ? (8u + (uint32_t)sub) : (uint32_t)sub;
    const uint32_t psend_h = mapa_u32(hloc, rank);
    const uint32_t psend_b = mapa_u32(bar0, rank);
    // which half barrier our DATA feeds at the destination (by source crank)
    const uint32_t src_half_off = (crank >= 8u) ? 8u : 0u;
    // which half barrier this thread WAITS on (by the half it reads)
    const uint32_t wait_half_off = (uint32_t)half * 8u;

    if (tid == 0) {
        mbar_init(bar0, 1);        // parity0 half A
        mbar_init(bar0 + 8, 1);    // parity0 half B
        mbar_init(bar0 + 16, 1);   // parity1 half A
        mbar_init(bar0 + 24, 1);   // parity1 half B
        asm volatile("fence.mbarrier_init.release.cluster;" ::: "memory");
        mbar_expect(bar0, 512);
        mbar_expect(bar0 + 8, 512);
        mbar_expect(bar0 + 16, 512);
        mbar_expect(bar0 + 24, 512);
    }
    __syncthreads();
    cluster_sync_all();

    // permuted gin index for this thread; prefetch 2 steps deep
    const size_t ginbase = (size_t)dir * TL * 1024 + (uglob * 4 + gate);
    float gin  = g_gin[ginbase + (size_t)(dir ? TL - 1 : 0) * 1024];
    float gin1 = g_gin[ginbase + (size_t)(dir ? TL - 2 : 1) * 1024];

    const uint32_t pairoff = (uint32_t)(16 * (int)crank + (u & ~1)) * 4u;

    for (int s = 0; s < TL; s++) {
        const int prev = (s + 1) & 1;
        const int cur  = s & 1;

        // prefetch step s+2's input projection (independent of the h chain)
        float ginN = 0.f;
        if (s + 2 < TL) {
            int tn = dir ? (TL - 3 - s) : (s + 2);
            ginN = g_gin[ginbase + (size_t)tn * 1024];
        }

        if (s > 0) {
            // wait only the half this thread reads (8 senders, 512 B)
            mbar_wait(bar0 + 16u * (uint32_t)prev + wait_half_off,
                      (uint32_t)(((s - 1) >> 1) & 1));
            // re-arm: one thread per half (tid 0 -> half A, tid 1 -> half B)
            if (tid < 2)
                mbar_expect(bar0 + 16u * (uint32_t)prev + 8u * (uint32_t)tid, 512);
        }

        // gate dot: 128 MACs/thread = 64 FFMA2, 8 accumulators (8-deep chains)
        const ulonglong2* hp2 = (const ulonglong2*)(hbuf + prev * HD + (half << 7));
        unsigned long long ac[8];
#pragma unroll
        for (int j = 0; j < 8; j++) ac[j] = 0ull;
#pragma unroll
        for (int j = 0; j < 8; j++) {
            ulonglong2 h01 = hp2[4 * j + 0];
            ulonglong2 h23 = hp2[4 * j + 1];
            ulonglong2 h45 = hp2[4 * j + 2];
            ulonglong2 h67 = hp2[4 * j + 3];
            fma2(ac[0], w[8 * j + 0], h01.x);
            fma2(ac[1], w[8 * j + 1], h01.y);
            fma2(ac[2], w[8 * j + 2], h23.x);
            fma2(ac[3], w[8 * j + 3], h23.y);
            fma2(ac[4], w[8 * j + 4], h45.x);
            fma2(ac[5], w[8 * j + 5], h45.y);
            fma2(ac[6], w[8 * j + 6], h67.x);
            fma2(ac[7], w[8 * j + 7], h67.y);
        }
        // packed f32x2 reduction tree: 4+2+1 packed adds, then one unpack
        unsigned long long r0 = add2(ac[0], ac[1]);
        unsigned long long r1 = add2(ac[2], ac[3]);
        unsigned long long r2 = add2(ac[4], ac[5]);
        unsigned long long r3 = add2(ac[6], ac[7]);
        unsigned long long r4 = add2(r0, r1);
        unsigned long long r5 = add2(r2, r3);
        float sum = sum2(add2(r4, r5));
        sum += __shfl_xor_sync(0xffffffffu, sum, 1);   // rendezvous of halves

        // branchless per-lane activation: a = k1 * sig(k2*v) + k0
        float v = sum + gin;
        float a = fmaf(k1, sig_f(k2 * v), k0);

        // gather all 4 gates within the 8-lane group
        int gb = lane & ~7;
        float gi = __shfl_sync(0xffffffffu, a, gb + 0);
        float gf = __shfl_sync(0xffffffffu, a, gb + 2);
        float gg = __shfl_sync(0xffffffffu, a, gb + 4);
        float go = __shfl_sync(0xffffffffu, a, gb + 6);

        creg = gf * creg + gi * gg;       // redundant on all 8 lanes
        float h = go * tanh_f(creg);

        // form the unit pair (h_even, h_odd) with a single xor-shfl
        float hother = __shfl_xor_sync(0xffffffffu, h, 8);
        float hlo = (u & 1) ? hother : h;
        float hhi = (u & 1) ? h      : hother;

        unsigned long long pk;
        asm("mov.b64 %0, {%1, %2};" : "=l"(pk)
            : "r"(__float_as_uint(hlo)), "r"(__float_as_uint(hhi)));
        st_async_u64(psend_h + (uint32_t)cur * (HD * 4u) + pairoff, pk,
                     psend_b + 16u * (uint32_t)cur + src_half_off);

        if (sub == 0) {
            int t = dir ? (TL - 1 - s) : s;
            g_hs[((size_t)dir * TL + t) * HD + uglob] = h;
        }
        gin = gin1;
        gin1 = ginN;
    }
    // drain: final phase of parity-1 barriers (s=2047 sends) = parity 1
    mbar_wait(bar0 + 16u + wait_half_off, 1u);
    cluster_sync_all();
}

// ---------------------------------------------------------------------------
// K3: feats[t][j] = b_out[j] + concat(h_f[t], h_b[t]) . W_out[j]
// ---------------------------------------------------------------------------
__global__ __launch_bounds__(256) void feats_kernel(
    const float* __restrict__ Wout, const float* __restrict__ bout)
{
    __shared__ float Ws[NT * 512];
    const int tid = threadIdx.x;
    for (int i = tid; i < NT * 512; i += 256) Ws[i] = Wout[i];
    __syncthreads();

    const int wid  = tid >> 5;
    const int lane = tid & 31;
    const int t = blockIdx.x * 8 + wid;
    if (t >= TL) return;

    float acc[NT];
#pragma unroll
    for (int j = 0; j < NT; j++) acc[j] = 0.f;

#pragma unroll
    for (int i = 0; i < 8; i++) {
        float hf = g_hs[((size_t)0 * TL + t) * HD + i * 32 + lane];
#pragma unroll
        for (int j = 0; j < NT; j++) acc[j] = fmaf(hf, Ws[j * 512 + i * 32 + lane], acc[j]);
    }
#pragma unroll
    for (int i = 0; i < 8; i++) {
        float hb = g_hs[((size_t)1 * TL + t) * HD + i * 32 + lane];
#pragma unroll
        for (int j = 0; j < NT; j++) acc[j] = fmaf(hb, Ws[j * 512 + 256 + i * 32 + lane], acc[j]);
    }
#pragma unroll
    for (int j = 0; j < NT; j++) {
#pragma unroll
        for (int off = 16; off >= 1; off >>= 1)
            acc[j] += __shfl_xor_sync(0xffffffffu, acc[j], off);
    }
    if (lane < NT) g_feats[t * NT + lane] = acc[lane] + bout[lane];
}

// ---------------------------------------------------------------------------
// K4a: per-chunk max-plus transfer matrices M_c[j][p] (16 blocks x 64 threads)
// ---------------------------------------------------------------------------
__global__ __launch_bounds__(64) void vit_chunkmat(const float* __restrict__ trans)
{
    __shared__ float fb[CS * NT];
    __shared__ float Vs[NT][NT + 1];
    const int c = blockIdx.x, tid = threadIdx.x;

    for (int i = tid; i < CS * NT; i += 64) fb[i] = g_feats[c * CS * NT + i];

    const bool act = tid < NT * NT;
    const int j = tid / NT, p = tid - j * NT;
    float Tr[NT];
    if (act) {
#pragma unroll
        for (int i = 0; i < NT; i++) Tr[i] = trans[j * NT + i];
        Vs[j][p] = (j == p) ? 0.f : -1e30f;
    }
    __syncthreads();

    for (int st = 0; st < CS; st++) {
        float v = 0.f;
        if (act) {
            float m = -3.4e38f;
#pragma unroll
            for (int i = 0; i < NT; i++) m = fmaxf(m, Vs[i][p] + Tr[i]);
            v = m + fb[st * NT + j];
        }
        __syncthreads();
        if (act) Vs[j][p] = v;
        __syncthreads();
    }
    if (act) g_M[c][j][p] = Vs[j][p];
}

// ---------------------------------------------------------------------------
// K4b: compose chunk matrices -> boundary fv's + terminal score/tag (1 warp)
// ---------------------------------------------------------------------------
__global__ __launch_bounds__(32) void vit_combine(const float* __restrict__ trans)
{
    const int lane = threadIdx.x;
    const int jj = (lane < NT) ? lane : (NT - 1);
    float fv = (jj == TAG_START) ? 0.f : NEGV;

    for (int c = 0; c < NCHUNK; c++) {
        if (lane < NT) g_fvb[c][lane] = fv;
        float row[NT];
#pragma unroll
        for (int p = 0; p < NT; p++) row[p] = g_M[c][jj][p];
        float nf = -3.4e38f;
#pragma unroll
        for (int p = 0; p < NT; p++) {
            float fvp = __shfl_sync(0xffffffffu, fv, p);
            nf = fmaxf(nf, row[p] + fvp);
        }
        fv = nf;
    }
    float term = fv + trans[TAG_END * NT + jj];
    float best = -3.4e38f;
    int arg = 0;
#pragma unroll
    for (int i = 0; i < NT; i++) {
        float vv = __shfl_sync(0xffffffffu, term, i);
        if (vv > best) { best = vv; arg = i; }
    }
    if (lane == 0) { g_final[0] = best; g_final[1] = (float)arg; }
}

// ---------------------------------------------------------------------------
// K4c: replay chunk DP from boundary fv, record bp, backtrack all 7 hypotheses
// ---------------------------------------------------------------------------
__global__ __launch_bounds__(256) void vit_replay(const float* __restrict__ trans)
{
    __shared__ float fb[CS * NT];
    __shared__ unsigned char bp[CS * NT];
    __shared__ unsigned char cand[NT][CS];
    const int c = blockIdx.x, tid = threadIdx.x;

    for (int i = tid; i < CS * NT; i += 256) fb[i] = g_feats[c * CS * NT + i];
    __syncthreads();

    if (tid < 32) {
        const int lane = tid;
        const int jj = (lane < NT) ? lane : (NT - 1);
        float fv = g_fvb[c][jj];
        float Tr[NT];
#pragma unroll
        for (int i = 0; i < NT; i++) Tr[i] = trans[jj * NT + i];

        for (int st = 0; st < CS; st++) {
            float best = -3.4e38f;
            int arg = 0;
#pragma unroll
            for (int i = 0; i < NT; i++) {
                float fvi = __shfl_sync(0xffffffffu, fv, i);
                float cnd = fvi + Tr[i];
                if (cnd > best) { best = cnd; arg = i; }
            }
            fv = best + fb[st * NT + jj];
            if (lane < NT) bp[st * NT + lane] = (unsigned char)arg;
        }
        if (lane < NT) {
            int tag = lane;
            for (int t = CS - 1; t >= 0; t--) {
                cand[lane][t] = (unsigned char)tag;
                tag = (int)bp[t * NT + tag];
            }
            g_exit[c][lane] = (unsigned char)tag;
        }
    }
    __syncthreads();
    for (int i = tid; i < NT * CS / 4; i += 256)
        ((uint32_t*)&g_cand[c][0][0])[i] = ((const uint32_t*)cand)[i];
}

// ---------------------------------------------------------------------------
// K4d: stitch chunks and emit output
// ---------------------------------------------------------------------------
__global__ __launch_bounds__(256) void vit_emit(float* __restrict__ out, int out_size)
{
    __shared__ int e[NCHUNK];
    __shared__ float sc;
    const int tid = threadIdx.x;
    if (tid == 0) {
        sc = g_final[0];
        int tag = (int)g_final[1];
        for (int c = NCHUNK - 1; c >= 0; c--) {
            e[c] = tag;
            tag = (int)g_exit[c][tag];
        }
    }
    __syncthreads();
    const int base = (out_size > TL) ? 1 : 0;
    if (tid == 0 && base) out[0] = sc;
    for (int i = tid; i < TL; i += 256) {
        int c = i >> 7;
        if (base + i < out_size)
            out[base + i] = (float)g_cand[c][e[c]][i & (CS - 1)];
    }
}

// ---------------------------------------------------------------------------
extern "C" void kernel_launch(void* const* d_in, const int* in_sizes, int n_in,
                              void* d_out, int out_size) {
    const int*   words = (const int*)  d_in[0];
    const float* embed = (const float*)d_in[1];
    const float* Wihf  = (const float*)d_in[2];
    const float* Whhf  = (const float*)d_in[3];
    const float* bihf  = (const float*)d_in[4];
    const float* bhhf  = (const float*)d_in[5];
    const float* Wihb  = (const float*)d_in[6];
    const float* Whhb  = (const float*)d_in[7];
    const float* bihb  = (const float*)d_in[8];
    const float* bhhb  = (const float*)d_in[9];
    const float* Wout  = (const float*)d_in[10];
    const float* bout  = (const float*)d_in[11];
    const float* trans = (const float*)d_in[12];
    const float* h0    = (const float*)d_in[13];
    const float* c0    = (const float*)d_in[14];
    float* out = (float*)d_out;

    // allow cluster size 16 (host-side attribute; executes at capture time)
    static int attr_set = 0;
    if (!attr_set) {
        cudaFuncSetAttribute(lstm_kernel,
                             cudaFuncAttributeNonPortableClusterSizeAllowed, 1);
        attr_set = 1;
    }

    gin_gemm<<<dim3(TL / 128, 8, 2), 256>>>(words, embed, Wihf, bihf, bhhf, Wihb, bihb, bhhb);
    lstm_kernel<<<2 * CLN, 128>>>(Whhf, Whhb, h0, c0);
    feats_kernel<<<TL / 8, 256>>>(Wout, bout);
    vit_chunkmat<<<NCHUNK, 64>>>(trans);
    vit_combine<<<1, 32>>>(trans);
    vit_replay<<<NCHUNK, 256>>>(trans);
    vit_emit<<<1, 256>>>(out, out_size);
}

// round 14
// speedup vs baseline: 2.0825x; 2.0825x over previous
#include <cuda_runtime.h>
#include <cuda_bf16.h>
#include <cstdint>
#include <math.h>

#define TL 2048
#define EMB 256
#define HD 256           // per-direction hidden
#define NT 7
#define TAG_START 5
#define TAG_END 6
#define NEGV -10000.0f
#define NCHUNK 16
#define CS 128           // chunk size (TL / NCHUNK)
#define CLN 16           // cluster size for lstm

// Scratch (device globals; no allocation allowed)
__device__ float g_gin[2 * TL * 1024];    // [dir][t][perm] permuted input projections
__device__ float g_hs[2 * TL * HD];       // [dir][t][HD]
__device__ float g_feats[TL * NT];
__device__ float g_M[NCHUNK][NT][NT];     // max-plus chunk matrices
__device__ float g_fvb[NCHUNK][NT];       // fv entering each chunk
__device__ float g_final[2];              // [path_score, final_tag]
__device__ unsigned char g_cand[NCHUNK][NT][CS];  // candidate paths per end-tag
__device__ unsigned char g_exit[NCHUNK][NT];      // exit tag per end-tag hypothesis

// ---------------------------------------------------------------------------
// PTX helpers
// ---------------------------------------------------------------------------
__device__ __forceinline__ uint32_t smem_u32(const void* p) {
    uint32_t a;
    asm("{ .reg .u64 t; cvta.to.shared.u64 t, %1; cvt.u32.u64 %0, t; }" : "=r"(a) : "l"(p));
    return a;
}
__device__ __forceinline__ uint32_t mapa_u32(uint32_t addr, uint32_t rank) {
    uint32_t r;
    asm("mapa.shared::cluster.u32 %0, %1, %2;" : "=r"(r) : "r"(addr), "r"(rank));
    return r;
}
__device__ __forceinline__ uint32_t my_ctarank() {
    uint32_t r;
    asm("mov.u32 %0, %%cluster_ctarank;" : "=r"(r));
    return r;
}
__device__ __forceinline__ void cluster_sync_all() {
    asm volatile("barrier.cluster.arrive.aligned;" ::: "memory");
    asm volatile("barrier.cluster.wait.aligned;" ::: "memory");
}
__device__ __forceinline__ void mbar_init(uint32_t a, uint32_t n) {
    asm volatile("mbarrier.init.shared.b64 [%0], %1;" :: "r"(a), "r"(n) : "memory");
}
__device__ __forceinline__ void mbar_expect(uint32_t a, uint32_t tx) {
    asm volatile("mbarrier.arrive.expect_tx.shared.b64 _, [%0], %1;" :: "r"(a), "r"(tx) : "memory");
}
__device__ __forceinline__ void mbar_wait(uint32_t a, uint32_t phase) {
    uint32_t done;
    asm volatile(
        "{\n\t.reg .pred p;\n\t"
        "mbarrier.try_wait.parity.acquire.cta.shared::cta.b64 p, [%1], %2;\n\t"
        "selp.b32 %0, 1, 0, p;\n\t}"
        : "=r"(done) : "r"(a), "r"(phase) : "memory");
    if (!done) {
        asm volatile(
            "{\n\t.reg .pred P;\n"
            "W%=:\n\t"
            "mbarrier.try_wait.parity.acquire.cta.shared::cta.b64 P, [%0], %1, 0x989680;\n\t"
            "@P bra D%=;\n\t"
            "bra W%=;\n"
            "D%=:\n\t}"
            :: "r"(a), "r"(phase) : "memory");
    }
}
__device__ __forceinline__ void st_async_u64(uint32_t daddr, unsigned long long v, uint32_t baddr) {
    asm volatile("st.async.shared::cluster.mbarrier::complete_tx::bytes.u64 [%0], %1, [%2];"
                 :: "r"(daddr), "l"(v), "r"(baddr) : "memory");
}
__device__ __forceinline__ void fma2(unsigned long long& d, unsigned long long a, unsigned long long b) {
    asm("fma.rn.f32x2 %0, %1, %2, %0;" : "+l"(d) : "l"(a), "l"(b));
}
__device__ __forceinline__ unsigned long long add2(unsigned long long a, unsigned long long b) {
    unsigned long long r;
    asm("add.rn.f32x2 %0, %1, %2;" : "=l"(r) : "l"(a), "l"(b));
    return r;
}
__device__ __forceinline__ float sum2(unsigned long long v) {
    uint32_t lo, hi;
    asm("mov.b64 {%0, %1}, %2;" : "=r"(lo), "=r"(hi) : "l"(v));
    return __uint_as_float(lo) + __uint_as_float(hi);
}
// fast activations: EX2-based exp + approx reciprocal (~2^-21 rel err)
__device__ __forceinline__ float sig_f(float x) {
    return __fdividef(1.f, 1.f + __expf(-x));
}
__device__ __forceinline__ float tanh_f(float x) {
    return 1.f - __fdividef(2.f, __expf(2.f * x) + 1.f);
}

// ---------------------------------------------------------------------------
// K1: input projection GEMM -> permuted layout matching K2's read order:
// perm index p = (row & 255) * 4 + (row >> 8)   (unit_global*4 + gate)
// ---------------------------------------------------------------------------
__global__ __launch_bounds__(256) void gin_gemm(
    const int* __restrict__ words, const float* __restrict__ embed,
    const float* __restrict__ Wf, const float* __restrict__ bif, const float* __restrict__ bhf,
    const float* __restrict__ Wb, const float* __restrict__ bib, const float* __restrict__ bhb)
{
    const int dir = blockIdx.z;
    const float* W  = dir ? Wb  : Wf;
    const float* bi = dir ? bib : bif;
    const float* bh = dir ? bhb : bhf;
    const int t0  = blockIdx.x * 128;
    const int r0  = blockIdx.y * 128;

    __shared__ float Xs[128][33];
    __shared__ float Ws[128][33];
    __shared__ int   sw[128];

    const int tid = threadIdx.x;
    const int tx = tid & 15, ty = tid >> 4;

    if (tid < 128) sw[tid] = words[t0 + tid];

    float acc[8][8];
#pragma unroll
    for (int i = 0; i < 8; i++)
#pragma unroll
        for (int j = 0; j < 8; j++) acc[i][j] = 0.f;

    for (int kb = 0; kb < EMB; kb += 32) {
        __syncthreads();
#pragma unroll
        for (int it = 0; it < 16; it++) {
            int idx = tid + it * 256;
            int r = idx >> 5, k = idx & 31;
            Xs[r][k] = embed[(size_t)sw[r] * EMB + kb + k];
        }
#pragma unroll
        for (int it = 0; it < 16; it++) {
            int idx = tid + it * 256;
            int r = idx >> 5, k = idx & 31;
            Ws[r][k] = W[(size_t)(r0 + r) * EMB + kb + k];
        }
        __syncthreads();
#pragma unroll
        for (int k = 0; k < 32; k++) {
            float xr[8], wr[8];
#pragma unroll
            for (int i = 0; i < 8; i++) xr[i] = Xs[ty + i * 16][k];
#pragma unroll
            for (int j = 0; j < 8; j++) wr[j] = Ws[tx + j * 16][k];
#pragma unroll
            for (int i = 0; i < 8; i++)
#pragma unroll
                for (int j = 0; j < 8; j++) acc[i][j] = fmaf(xr[i], wr[j], acc[i][j]);
        }
    }
#pragma unroll
    for (int j = 0; j < 8; j++) {
        int row = r0 + tx + j * 16;
        float bb = bi[row] + bh[row];
        int p = (row & 255) * 4 + (row >> 8);
#pragma unroll
        for (int i = 0; i < 8; i++) {
            int t = t0 + ty + i * 16;
            g_gin[((size_t)dir * TL + t) * 1024 + p] = acc[i][j] + bb;
        }
    }
}

// ---------------------------------------------------------------------------
// K2: sequential BiLSTM. Two 16-CTA clusters (one per direction), 128 thr/CTA.
// Each CTA: 16 units = 64 gate rows. u = tid>>3, sub = tid&7, gate = sub>>1,
// half = sub&1. Whh half-row (128 floats) in registers as 64 f32x2.
// h broadcast: unit-pairs packed u64 via st.async; even-u groups -> ranks 0-7,
// odd-u groups -> ranks 8-15. 128 sends/CTA, expect_tx = 1024 B per barrier.
// Single per-parity barrier => warp-uniform wait (split barriers diverge the
// poll loop intra-warp and serialize both waits — measured 2x regression).
// gin prefetched 2 steps ahead. Branchless activation; 8-acc FFMA2 dot;
// packed f32x2 reduction tree.
// ---------------------------------------------------------------------------
__global__ __launch_bounds__(128, 1) __cluster_dims__(CLN, 1, 1)
void lstm_kernel(const float* __restrict__ Whf, const float* __restrict__ Whb,
                 const float* __restrict__ h0, const float* __restrict__ c0)
{
    __shared__ __align__(16) float hbuf[2 * HD];
    __shared__ __align__(8) unsigned long long bars[2];

    const int tid = threadIdx.x;
    const int dir = blockIdx.x >> 4;
    const uint32_t crank = my_ctarank();

    const int u    = tid >> 3;        // 0..15 local unit
    const int sub  = tid & 7;         // lane within unit group
    const int gate = sub >> 1;        // 0..3
    const int half = sub & 1;         // k-half
    const int lane = tid & 31;
    const int uglob = 16 * (int)crank + u;
    const int grow = gate * 256 + uglob;           // global gate row
    const float* Wh = dir ? Whb : Whf;

    // branchless activation constants: a = k1 * sig(k2*v) + k0
    const float k2 = (gate == 2) ? 2.f : 1.f;
    const float k1 = k2;
    const float k0 = (gate == 2) ? -1.f : 0.f;

    // Whh half-row -> registers: 128 floats as 64 f32x2
    unsigned long long w[64];
    {
        const unsigned long long* wp =
            (const unsigned long long*)(Wh + (size_t)grow * HD + (half << 7));
#pragma unroll
        for (int j = 0; j < 64; j++) w[j] = wp[j];
    }

    // init: h(-1) in slot 1 (prev at s=0); c0 redundant on all 8 lanes of group
    hbuf[HD + tid] = h0[dir * HD + tid];
    hbuf[HD + 128 + tid] = h0[dir * HD + 128 + tid];
    float creg = c0[dir * HD + uglob];

    const uint32_t hloc = smem_u32(hbuf);
    const uint32_t bar0 = smem_u32(&bars[0]);
    const uint32_t rank = (u & 1) ? (8u + (uint32_t)sub) : (uint32_t)sub;
    const uint32_t psend_h = mapa_u32(hloc, rank);
    const uint32_t psend_b = mapa_u32(bar0, rank);

    if (tid == 0) {
        mbar_init(bar0, 1);
        mbar_init(bar0 + 8, 1);
        asm volatile("fence.mbarrier_init.release.cluster;" ::: "memory");
        mbar_expect(bar0, 1024);
        mbar_expect(bar0 + 8, 1024);
    }
    __syncthreads();
    cluster_sync_all();

    // permuted gin index for this thread; prefetch 2 steps deep
    const size_t ginbase = (size_t)dir * TL * 1024 + (uglob * 4 + gate);
    float gin  = g_gin[ginbase + (size_t)(dir ? TL - 1 : 0) * 1024];
    float gin1 = g_gin[ginbase + (size_t)(dir ? TL - 2 : 1) * 1024];

    const uint32_t pairoff = (uint32_t)(16 * (int)crank + (u & ~1)) * 4u;
    const bool odd_u = (u & 1) != 0;

    for (int s = 0; s < TL; s++) {
        const int prev = (s + 1) & 1;
        const int cur  = s & 1;

        // prefetch step s+2's input projection (independent of the h chain)
        float ginN = 0.f;
        if (s + 2 < TL) {
            int tn = dir ? (TL - 3 - s) : (s + 2);
            ginN = g_gin[ginbase + (size_t)tn * 1024];
        }

        if (s > 0) {
            mbar_wait(bar0 + 8u * (uint32_t)prev, (uint32_t)(((s - 1) >> 1) & 1));
            if (tid == 0) mbar_expect(bar0 + 8u * (uint32_t)prev, 1024);
        }

        // gate dot: 128 MACs/thread = 64 FFMA2, 8 accumulators (8-deep chains)
        const ulonglong2* hp2 = (const ulonglong2*)(hbuf + prev * HD + (half << 7));
        unsigned long long ac[8];
#pragma unroll
        for (int j = 0; j < 8; j++) ac[j] = 0ull;
#pragma unroll
        for (int j = 0; j < 8; j++) {
            ulonglong2 h01 = hp2[4 * j + 0];
            ulonglong2 h23 = hp2[4 * j + 1];
            ulonglong2 h45 = hp2[4 * j + 2];
            ulonglong2 h67 = hp2[4 * j + 3];
            fma2(ac[0], w[8 * j + 0], h01.x);
            fma2(ac[1], w[8 * j + 1], h01.y);
            fma2(ac[2], w[8 * j + 2], h23.x);
            fma2(ac[3], w[8 * j + 3], h23.y);
            fma2(ac[4], w[8 * j + 4], h45.x);
            fma2(ac[5], w[8 * j + 5], h45.y);
            fma2(ac[6], w[8 * j + 6], h67.x);
            fma2(ac[7], w[8 * j + 7], h67.y);
        }
        // packed f32x2 reduction tree: 4+2+1 packed adds, then one unpack
        unsigned long long r0 = add2(ac[0], ac[1]);
        unsigned long long r1 = add2(ac[2], ac[3]);
        unsigned long long r2 = add2(ac[4], ac[5]);
        unsigned long long r3 = add2(ac[6], ac[7]);
        unsigned long long r4 = add2(r0, r1);
        unsigned long long r5 = add2(r2, r3);
        float sum = sum2(add2(r4, r5));
        sum += __shfl_xor_sync(0xffffffffu, sum, 1);   // reduce halves

        // branchless per-lane activation: a = k1 * sig(k2*v) + k0
        float v = sum + gin;
        float a = fmaf(k1, sig_f(k2 * v), k0);

        // gather all 4 gates within the 8-lane group
        int gb = lane & ~7;
        float gi = __shfl_sync(0xffffffffu, a, gb + 0);
        float gf = __shfl_sync(0xffffffffu, a, gb + 2);
        float gg = __shfl_sync(0xffffffffu, a, gb + 4);
        float go = __shfl_sync(0xffffffffu, a, gb + 6);

        creg = gf * creg + gi * gg;       // redundant on all 8 lanes
        float h = go * tanh_f(creg);

        // form the unit pair (h_even, h_odd) with a single xor-shfl
        float hother = __shfl_xor_sync(0xffffffffu, h, 8);
        float hlo = odd_u ? hother : h;
        float hhi = odd_u ? h      : hother;

        unsigned long long pk;
        asm("mov.b64 %0, {%1, %2};" : "=l"(pk)
            : "r"(__float_as_uint(hlo)), "r"(__float_as_uint(hhi)));
        st_async_u64(psend_h + (uint32_t)cur * (HD * 4u) + pairoff, pk,
                     psend_b + 8u * (uint32_t)cur);

        if (sub == 0) {
            int t = dir ? (TL - 1 - s) : s;
            g_hs[((size_t)dir * TL + t) * HD + uglob] = h;
        }
        gin = gin1;
        gin1 = ginN;
    }
    // h(2047) completion = bar[1]'s final phase -> parity 1
    mbar_wait(bar0 + 8, 1u);
    cluster_sync_all();
}

// ---------------------------------------------------------------------------
// K3: feats[t][j] = b_out[j] + concat(h_f[t], h_b[t]) . W_out[j]
// ---------------------------------------------------------------------------
__global__ __launch_bounds__(256) void feats_kernel(
    const float* __restrict__ Wout, const float* __restrict__ bout)
{
    __shared__ float Ws[NT * 512];
    const int tid = threadIdx.x;
    for (int i = tid; i < NT * 512; i += 256) Ws[i] = Wout[i];
    __syncthreads();

    const int wid  = tid >> 5;
    const int lane = tid & 31;
    const int t = blockIdx.x * 8 + wid;
    if (t >= TL) return;

    float acc[NT];
#pragma unroll
    for (int j = 0; j < NT; j++) acc[j] = 0.f;

#pragma unroll
    for (int i = 0; i < 8; i++) {
        float hf = g_hs[((size_t)0 * TL + t) * HD + i * 32 + lane];
#pragma unroll
        for (int j = 0; j < NT; j++) acc[j] = fmaf(hf, Ws[j * 512 + i * 32 + lane], acc[j]);
    }
#pragma unroll
    for (int i = 0; i < 8; i++) {
        float hb = g_hs[((size_t)1 * TL + t) * HD + i * 32 + lane];
#pragma unroll
        for (int j = 0; j < NT; j++) acc[j] = fmaf(hb, Ws[j * 512 + 256 + i * 32 + lane], acc[j]);
    }
#pragma unroll
    for (int j = 0; j < NT; j++) {
#pragma unroll
        for (int off = 16; off >= 1; off >>= 1)
            acc[j] += __shfl_xor_sync(0xffffffffu, acc[j], off);
    }
    if (lane < NT) g_feats[t * NT + lane] = acc[lane] + bout[lane];
}

// ---------------------------------------------------------------------------
// K4a: per-chunk max-plus transfer matrices M_c[j][p] (16 blocks x 64 threads)
// ---------------------------------------------------------------------------
__global__ __launch_bounds__(64) void vit_chunkmat(const float* __restrict__ trans)
{
    __shared__ float fb[CS * NT];
    __shared__ float Vs[NT][NT + 1];
    const int c = blockIdx.x, tid = threadIdx.x;

    for (int i = tid; i < CS * NT; i += 64) fb[i] = g_feats[c * CS * NT + i];

    const bool act = tid < NT * NT;
    const int j = tid / NT, p = tid - j * NT;
    float Tr[NT];
    if (act) {
#pragma unroll
        for (int i = 0; i < NT; i++) Tr[i] = trans[j * NT + i];
        Vs[j][p] = (j == p) ? 0.f : -1e30f;
    }
    __syncthreads();

    for (int st = 0; st < CS; st++) {
        float v = 0.f;
        if (act) {
            float m = -3.4e38f;
#pragma unroll
            for (int i = 0; i < NT; i++) m = fmaxf(m, Vs[i][p] + Tr[i]);
            v = m + fb[st * NT + j];
        }
        __syncthreads();
        if (act) Vs[j][p] = v;
        __syncthreads();
    }
    if (act) g_M[c][j][p] = Vs[j][p];
}

// ---------------------------------------------------------------------------
// K4b: compose chunk matrices -> boundary fv's + terminal score/tag (1 warp)
// ---------------------------------------------------------------------------
__global__ __launch_bounds__(32) void vit_combine(const float* __restrict__ trans)
{
    const int lane = threadIdx.x;
    const int jj = (lane < NT) ? lane : (NT - 1);
    float fv = (jj == TAG_START) ? 0.f : NEGV;

    for (int c = 0; c < NCHUNK; c++) {
        if (lane < NT) g_fvb[c][lane] = fv;
        float row[NT];
#pragma unroll
        for (int p = 0; p < NT; p++) row[p] = g_M[c][jj][p];
        float nf = -3.4e38f;
#pragma unroll
        for (int p = 0; p < NT; p++) {
            float fvp = __shfl_sync(0xffffffffu, fv, p);
            nf = fmaxf(nf, row[p] + fvp);
        }
        fv = nf;
    }
    float term = fv + trans[TAG_END * NT + jj];
    float best = -3.4e38f;
    int arg = 0;
#pragma unroll
    for (int i = 0; i < NT; i++) {
        float vv = __shfl_sync(0xffffffffu, term, i);
        if (vv > best) { best = vv; arg = i; }
    }
    if (lane == 0) { g_final[0] = best; g_final[1] = (float)arg; }
}

// ---------------------------------------------------------------------------
// K4c: replay chunk DP from boundary fv, record bp, backtrack all 7 hypotheses
// ---------------------------------------------------------------------------
__global__ __launch_bounds__(256) void vit_replay(const float* __restrict__ trans)
{
    __shared__ float fb[CS * NT];
    __shared__ unsigned char bp[CS * NT];
    __shared__ unsigned char cand[NT][CS];
    const int c = blockIdx.x, tid = threadIdx.x;

    for (int i = tid; i < CS * NT; i += 256) fb[i] = g_feats[c * CS * NT + i];
    __syncthreads();

    if (tid < 32) {
        const int lane = tid;
        const int jj = (lane < NT) ? lane : (NT - 1);
        float fv = g_fvb[c][jj];
        float Tr[NT];
#pragma unroll
        for (int i = 0; i < NT; i++) Tr[i] = trans[jj * NT + i];

        for (int st = 0; st < CS; st++) {
            float best = -3.4e38f;
            int arg = 0;
#pragma unroll
            for (int i = 0; i < NT; i++) {
                float fvi = __shfl_sync(0xffffffffu, fv, i);
                float cnd = fvi + Tr[i];
                if (cnd > best) { best = cnd; arg = i; }
            }
            fv = best + fb[st * NT + jj];
            if (lane < NT) bp[st * NT + lane] = (unsigned char)arg;
        }
        if (lane < NT) {
            int tag = lane;
            for (int t = CS - 1; t >= 0; t--) {
                cand[lane][t] = (unsigned char)tag;
                tag = (int)bp[t * NT + tag];
            }
            g_exit[c][lane] = (unsigned char)tag;
        }
    }
    __syncthreads();
    for (int i = tid; i < NT * CS / 4; i += 256)
        ((uint32_t*)&g_cand[c][0][0])[i] = ((const uint32_t*)cand)[i];
}

// ---------------------------------------------------------------------------
// K4d: stitch chunks and emit output
// ---------------------------------------------------------------------------
__global__ __launch_bounds__(256) void vit_emit(float* __restrict__ out, int out_size)
{
    __shared__ int e[NCHUNK];
    __shared__ float sc;
    const int tid = threadIdx.x;
    if (tid == 0) {
        sc = g_final[0];
        int tag = (int)g_final[1];
        for (int c = NCHUNK - 1; c >= 0; c--) {
            e[c] = tag;
            tag = (int)g_exit[c][tag];
        }
    }
    __syncthreads();
    const int base = (out_size > TL) ? 1 : 0;
    if (tid == 0 && base) out[0] = sc;
    for (int i = tid; i < TL; i += 256) {
        int c = i >> 7;
        if (base + i < out_size)
            out[base + i] = (float)g_cand[c][e[c]][i & (CS - 1)];
    }
}

// ---------------------------------------------------------------------------
extern "C" void kernel_launch(void* const* d_in, const int* in_sizes, int n_in,
                              void* d_out, int out_size) {
    const int*   words = (const int*)  d_in[0];
    const float* embed = (const float*)d_in[1];
    const float* Wihf  = (const float*)d_in[2];
    const float* Whhf  = (const float*)d_in[3];
    const float* bihf  = (const float*)d_in[4];
    const float* bhhf  = (const float*)d_in[5];
    const float* Wihb  = (const float*)d_in[6];
    const float* Whhb  = (const float*)d_in[7];
    const float* bihb  = (const float*)d_in[8];
    const float* bhhb  = (const float*)d_in[9];
    const float* Wout  = (const float*)d_in[10];
    const float* bout  = (const float*)d_in[11];
    const float* trans = (const float*)d_in[12];
    const float* h0    = (const float*)d_in[13];
    const float* c0    = (const float*)d_in[14];
    float* out = (float*)d_out;

    // allow cluster size 16 (host-side attribute; executes at capture time)
    static int attr_set = 0;
    if (!attr_set) {
        cudaFuncSetAttribute(lstm_kernel,
                             cudaFuncAttributeNonPortableClusterSizeAllowed, 1);
        attr_set = 1;
    }

    gin_gemm<<<dim3(TL / 128, 8, 2), 256>>>(words, embed, Wihf, bihf, bhhf, Wihb, bihb, bhhb);
    lstm_kernel<<<2 * CLN, 128>>>(Whhf, Whhb, h0, c0);
    feats_kernel<<<TL / 8, 256>>>(Wout, bout);
    vit_chunkmat<<<NCHUNK, 64>>>(trans);
    vit_combine<<<1, 32>>>(trans);
    vit_replay<<<NCHUNK, 256>>>(trans);
    vit_emit<<<1, 256>>>(out, out_size);
}